// round 1
// baseline (speedup 1.0000x reference)
#include <cuda_runtime.h>
#include <math.h>

// Problem constants
#define BDIM 4096   // trajectories
#define HDIM 1024   // GRU state
#define SDIM 256    // stochastic latent
#define NSAMP 256
#define TSTEPS 10
#define RHDIM 512   // reward hidden
#define N3 3072     // Wx/Wh leading dim (3*H)
// GEMM tiling
#define BM 64
#define BN 64
#define BK 16

// Persistent scratch (allocation-free: __device__ globals)
__device__ float g_h[2][BDIM * HDIM];     // ping-pong GRU state, 2 x 16MB
__device__ float g_s[BDIM * SDIM];        // stochastic latent, 4MB
__device__ float g_relu[BDIM * RHDIM];    // reward hidden activations, 8MB
__device__ float g_acc[BDIM];             // discounted (reward + epistemic) accumulator

__device__ __forceinline__ float sigm_(float x) { return 1.0f / (1.0f + expf(-x)); }
__device__ __forceinline__ float softplus_(float x) {
    return fmaxf(x, 0.0f) + log1pf(expf(-fabsf(x)));
}

// ---------------------------------------------------------------------------
// init: broadcast h0/s0 to all B rows, zero accumulator
// ---------------------------------------------------------------------------
__global__ void k_init(const float* __restrict__ h0, const float* __restrict__ s0) {
    int idx = blockIdx.x * blockDim.x + threadIdx.x;
    int stride = gridDim.x * blockDim.x;
    for (int i = idx; i < BDIM * HDIM; i += stride) g_h[0][i] = h0[i & (HDIM - 1)];
    for (int i = idx; i < BDIM * SDIM; i += stride) g_s[i] = s0[i & (SDIM - 1)];
    for (int i = idx; i < BDIM; i += stride) g_acc[i] = 0.0f;
}

// ---------------------------------------------------------------------------
// K1: fused GRU gates GEMM + h update.
//   per output (b, j in [0,H)):
//     zsum = sum_k u[k] * W(k, j)          (u = [s(256), h(1024)], W = [Wx;Wh])
//     rsum = sum_k u[k] * W(k, H + j)
//     nx   = sum_{k<256} s[k] * Wx(k, 2H + j)
//     nh   = sum_{k>=256} h[k] * Wh(k, 2H + j)
//   epilogue adds the action one-hot row of Wx and the biases, applies gates.
// grid (B/BM=64, H/BN=16), 256 threads, 4x4 per thread.
// ---------------------------------------------------------------------------
__global__ __launch_bounds__(256)
void k1_gru(int par,
            const float* __restrict__ Wx, const float* __restrict__ Wh,
            const float* __restrict__ b_gru, const int* __restrict__ acts_t) {
    const float* __restrict__ h_in = g_h[par];
    float* __restrict__ h_out = g_h[par ^ 1];

    __shared__ float Us[BM][BK + 4];
    __shared__ float Wzs[BK][BN];
    __shared__ float Wrs[BK][BN];
    __shared__ float Wns[BK][BN];

    const int tid = threadIdx.x;
    const int tx = tid & 15;
    const int ty = tid >> 4;
    const int row0 = blockIdx.x * BM;
    const int col0 = blockIdx.y * BN;

    const int um = tid >> 2;            // 0..63 (row within tile)
    const int uk = (tid & 3) * 4;       // 0,4,8,12 (k within tile)
    const int wr_ = tid >> 4;           // 0..15 (k row for weight tile)
    const int wc = (tid & 15) * 4;      // col*4 for weight tile

    float accZ[4][4] = {}, accR[4][4] = {}, accN[4][4] = {}, accNX[4][4];

    const int KT_X = SDIM / BK;   // 16 tiles from the x (s) region
    const int KT_ALL = KT_X + HDIM / BK;  // 80 total

#pragma unroll 1
    for (int kt = 0; kt < KT_ALL; ++kt) {
        if (kt == KT_X) {
            // end of x region: save n's x-part, restart accumulator for h-part
#pragma unroll
            for (int i = 0; i < 4; i++)
#pragma unroll
                for (int j = 0; j < 4; j++) { accNX[i][j] = accN[i][j]; accN[i][j] = 0.0f; }
        }
        const bool xr = (kt < KT_X);
        const int k0 = xr ? kt * BK : (kt - KT_X) * BK;

        const float* ub = xr ? (g_s + (size_t)(row0 + um) * SDIM + k0 + uk)
                             : (h_in + (size_t)(row0 + um) * HDIM + k0 + uk);
        float4 uv = *(const float4*)ub;
        const float* wb = (xr ? Wx : Wh) + (size_t)(k0 + wr_) * N3 + col0 + wc;
        float4 wz = *(const float4*)(wb);
        float4 wrv = *(const float4*)(wb + HDIM);
        float4 wn = *(const float4*)(wb + 2 * HDIM);

        __syncthreads();
        *(float4*)&Us[um][uk] = uv;
        *(float4*)&Wzs[wr_][wc] = wz;
        *(float4*)&Wrs[wr_][wc] = wrv;
        *(float4*)&Wns[wr_][wc] = wn;
        __syncthreads();

#pragma unroll
        for (int kk = 0; kk < BK; ++kk) {
            float u[4];
#pragma unroll
            for (int i = 0; i < 4; i++) u[i] = Us[ty * 4 + i][kk];
            float4 z4 = *(const float4*)&Wzs[kk][tx * 4];
            float4 r4 = *(const float4*)&Wrs[kk][tx * 4];
            float4 n4 = *(const float4*)&Wns[kk][tx * 4];
            float zc[4] = { z4.x, z4.y, z4.z, z4.w };
            float rc[4] = { r4.x, r4.y, r4.z, r4.w };
            float nc[4] = { n4.x, n4.y, n4.z, n4.w };
#pragma unroll
            for (int i = 0; i < 4; i++) {
#pragma unroll
                for (int j = 0; j < 4; j++) {
                    accZ[i][j] = fmaf(u[i], zc[j], accZ[i][j]);
                    accR[i][j] = fmaf(u[i], rc[j], accR[i][j]);
                    accN[i][j] = fmaf(u[i], nc[j], accN[i][j]);
                }
            }
        }
    }

    // epilogue
#pragma unroll
    for (int i = 0; i < 4; i++) {
        int b = row0 + ty * 4 + i;
        int a = acts_t[b];
        const float* wa = Wx + (size_t)(SDIM + a) * N3;
#pragma unroll
        for (int j = 0; j < 4; j++) {
            int c = col0 + tx * 4 + j;
            float z = sigm_(accZ[i][j] + wa[c] + b_gru[c]);
            float r = sigm_(accR[i][j] + wa[HDIM + c] + b_gru[HDIM + c]);
            float n = tanhf(accNX[i][j] + wa[2 * HDIM + c] + r * accN[i][j] + b_gru[2 * HDIM + c]);
            float hp = h_in[(size_t)b * HDIM + c];
            h_out[(size_t)b * HDIM + c] = (1.0f - z) * hp + z * n;
        }
    }
}

// ---------------------------------------------------------------------------
// K2: mu/std GEMM (K=1024, N=256, two accumulators per cell) + latent sample.
// grid (64, 4), 256 threads, 4x4 per thread.
// ---------------------------------------------------------------------------
__global__ __launch_bounds__(256)
void k2_latent(int parn,
               const float* __restrict__ W_mu, const float* __restrict__ b_mu,
               const float* __restrict__ W_std, const float* __restrict__ b_std,
               const float* __restrict__ noise_t) {
    const float* __restrict__ h_new = g_h[parn];

    __shared__ float Hs[BM][BK + 4];
    __shared__ float Wm[BK][BN];
    __shared__ float Wv[BK][BN];

    const int tid = threadIdx.x;
    const int tx = tid & 15;
    const int ty = tid >> 4;
    const int row0 = blockIdx.x * BM;
    const int col0 = blockIdx.y * BN;

    const int um = tid >> 2;
    const int uk = (tid & 3) * 4;
    const int wr_ = tid >> 4;
    const int wc = (tid & 15) * 4;

    float accM[4][4] = {}, accS[4][4] = {};

#pragma unroll 1
    for (int kt = 0; kt < HDIM / BK; ++kt) {
        const int k0 = kt * BK;
        float4 hv = *(const float4*)(h_new + (size_t)(row0 + um) * HDIM + k0 + uk);
        float4 wm = *(const float4*)(W_mu + (size_t)(k0 + wr_) * SDIM + col0 + wc);
        float4 wv = *(const float4*)(W_std + (size_t)(k0 + wr_) * SDIM + col0 + wc);

        __syncthreads();
        *(float4*)&Hs[um][uk] = hv;
        *(float4*)&Wm[wr_][wc] = wm;
        *(float4*)&Wv[wr_][wc] = wv;
        __syncthreads();

#pragma unroll
        for (int kk = 0; kk < BK; ++kk) {
            float u[4];
#pragma unroll
            for (int i = 0; i < 4; i++) u[i] = Hs[ty * 4 + i][kk];
            float4 m4 = *(const float4*)&Wm[kk][tx * 4];
            float4 v4 = *(const float4*)&Wv[kk][tx * 4];
            float mc[4] = { m4.x, m4.y, m4.z, m4.w };
            float vc[4] = { v4.x, v4.y, v4.z, v4.w };
#pragma unroll
            for (int i = 0; i < 4; i++) {
#pragma unroll
                for (int j = 0; j < 4; j++) {
                    accM[i][j] = fmaf(u[i], mc[j], accM[i][j]);
                    accS[i][j] = fmaf(u[i], vc[j], accS[i][j]);
                }
            }
        }
    }

#pragma unroll
    for (int i = 0; i < 4; i++) {
        int b = row0 + ty * 4 + i;
#pragma unroll
        for (int j = 0; j < 4; j++) {
            int c = col0 + tx * 4 + j;
            float mu = accM[i][j] + b_mu[c];
            float sl = accS[i][j] + b_std[c];
            float sd = softplus_(sl) + 0.1f;
            g_s[(size_t)b * SDIM + c] = mu + sd * noise_t[(size_t)b * SDIM + c];
        }
    }
}

// ---------------------------------------------------------------------------
// K3: reward hidden GEMM: relu(feat @ W_r1 + b_r1), feat = [h_new, s_new].
// grid (64, 8), 256 threads, 4x4 per thread. K=1280 split at 1024.
// ---------------------------------------------------------------------------
__global__ __launch_bounds__(256)
void k3_reward(int parn, const float* __restrict__ W_r1, const float* __restrict__ b_r1) {
    const float* __restrict__ h_new = g_h[parn];

    __shared__ float Fs[BM][BK + 4];
    __shared__ float Ws[BK][BN];

    const int tid = threadIdx.x;
    const int tx = tid & 15;
    const int ty = tid >> 4;
    const int row0 = blockIdx.x * BM;
    const int col0 = blockIdx.y * BN;

    const int um = tid >> 2;
    const int uk = (tid & 3) * 4;
    const int wr_ = tid >> 4;
    const int wc = (tid & 15) * 4;

    float acc[4][4] = {};

    const int KT_H = HDIM / BK;       // 64
    const int KT_ALL = KT_H + SDIM / BK;  // 80

#pragma unroll 1
    for (int kt = 0; kt < KT_ALL; ++kt) {
        const bool hr = (kt < KT_H);
        const int k0 = hr ? kt * BK : (kt - KT_H) * BK;
        const int kglob = hr ? k0 : (HDIM + k0);

        const float* ub = hr ? (h_new + (size_t)(row0 + um) * HDIM + k0 + uk)
                             : (g_s + (size_t)(row0 + um) * SDIM + k0 + uk);
        float4 fv = *(const float4*)ub;
        float4 wv = *(const float4*)(W_r1 + (size_t)(kglob + wr_) * RHDIM + col0 + wc);

        __syncthreads();
        *(float4*)&Fs[um][uk] = fv;
        *(float4*)&Ws[wr_][wc] = wv;
        __syncthreads();

#pragma unroll
        for (int kk = 0; kk < BK; ++kk) {
            float u[4];
#pragma unroll
            for (int i = 0; i < 4; i++) u[i] = Fs[ty * 4 + i][kk];
            float4 w4 = *(const float4*)&Ws[kk][tx * 4];
            float wcv[4] = { w4.x, w4.y, w4.z, w4.w };
#pragma unroll
            for (int i = 0; i < 4; i++) {
#pragma unroll
                for (int j = 0; j < 4; j++) {
                    acc[i][j] = fmaf(u[i], wcv[j], acc[i][j]);
                }
            }
        }
    }

#pragma unroll
    for (int i = 0; i < 4; i++) {
        int b = row0 + ty * 4 + i;
#pragma unroll
        for (int j = 0; j < 4; j++) {
            int c = col0 + tx * 4 + j;
            g_relu[(size_t)b * RHDIM + c] = fmaxf(acc[i][j] + b_r1[c], 0.0f);
        }
    }
}

// ---------------------------------------------------------------------------
// K4: per-row reduction. reward = relu_row . w_r2 + b_r2; var(feat);
//     g_acc[b] += disc * (reward + var).
// grid (4096), 128 threads.
// ---------------------------------------------------------------------------
__global__ void k4_reduce(int parn, const float* __restrict__ w_r2,
                          const float* __restrict__ b_r2, float disc) {
    const int b = blockIdx.x;
    const int tid = threadIdx.x;
    const float* __restrict__ hr = g_h[parn] + (size_t)b * HDIM;
    const float* __restrict__ sr = g_s + (size_t)b * SDIM;
    const float* __restrict__ rr = g_relu + (size_t)b * RHDIM;

    float sum = 0.0f, sq = 0.0f, dot = 0.0f;
    for (int k = tid; k < HDIM; k += 128) { float v = hr[k]; sum += v; sq = fmaf(v, v, sq); }
    for (int k = tid; k < SDIM; k += 128) { float v = sr[k]; sum += v; sq = fmaf(v, v, sq); }
    for (int k = tid; k < RHDIM; k += 128) dot = fmaf(rr[k], w_r2[k], dot);

#pragma unroll
    for (int off = 16; off > 0; off >>= 1) {
        sum += __shfl_down_sync(0xffffffffu, sum, off);
        sq  += __shfl_down_sync(0xffffffffu, sq, off);
        dot += __shfl_down_sync(0xffffffffu, dot, off);
    }
    __shared__ float s1[4], s2[4], s3[4];
    if ((tid & 31) == 0) { s1[tid >> 5] = sum; s2[tid >> 5] = sq; s3[tid >> 5] = dot; }
    __syncthreads();
    if (tid == 0) {
        float S = s1[0] + s1[1] + s1[2] + s1[3];
        float Q = s2[0] + s2[1] + s2[2] + s2[3];
        float D = s3[0] + s3[1] + s3[2] + s3[3];
        float mean = S * (1.0f / 1280.0f);
        float var = Q * (1.0f / 1280.0f) - mean * mean;
        float reward = D + b_r2[0];
        g_acc[b] += disc * (reward + var);
    }
}

// ---------------------------------------------------------------------------
// final: out[a] = -mean over 256 samples of g_acc
// ---------------------------------------------------------------------------
__global__ void k_final(float* __restrict__ out) {
    const int a = blockIdx.x;
    const int tid = threadIdx.x;  // 256 threads
    float v = g_acc[a * NSAMP + tid];
#pragma unroll
    for (int off = 16; off > 0; off >>= 1) v += __shfl_down_sync(0xffffffffu, v, off);
    __shared__ float w[8];
    if ((tid & 31) == 0) w[tid >> 5] = v;
    __syncthreads();
    if (tid < 8) {
        float x = w[tid];
#pragma unroll
        for (int off = 4; off > 0; off >>= 1) x += __shfl_down_sync(0xffu, x, off);
        if (tid == 0) out[a] = -x * (1.0f / (float)NSAMP);
    }
}

// ---------------------------------------------------------------------------
extern "C" void kernel_launch(void* const* d_in, const int* in_sizes, int n_in,
                              void* d_out, int out_size) {
    (void)in_sizes; (void)n_in; (void)out_size;
    const float* h0    = (const float*)d_in[0];
    const float* s0    = (const float*)d_in[1];
    const float* noise = (const float*)d_in[2];
    const float* Wx    = (const float*)d_in[3];
    const float* Wh    = (const float*)d_in[4];
    const float* b_gru = (const float*)d_in[5];
    const float* W_mu  = (const float*)d_in[6];
    const float* b_mu  = (const float*)d_in[7];
    const float* W_std = (const float*)d_in[8];
    const float* b_std = (const float*)d_in[9];
    const float* W_r1  = (const float*)d_in[10];
    const float* b_r1  = (const float*)d_in[11];
    const float* w_r2  = (const float*)d_in[12];
    const float* b_r2  = (const float*)d_in[13];
    const int*   acts  = (const int*)d_in[14];
    float* out = (float*)d_out;

    k_init<<<512, 256>>>(h0, s0);

    float disc = 1.0f;
    for (int t = 0; t < TSTEPS; ++t) {
        int par = t & 1;
        int parn = par ^ 1;
        k1_gru<<<dim3(BDIM / BM, HDIM / BN), 256>>>(par, Wx, Wh, b_gru, acts + (size_t)t * BDIM);
        k2_latent<<<dim3(BDIM / BM, SDIM / BN), 256>>>(parn, W_mu, b_mu, W_std, b_std,
                                                       noise + (size_t)t * BDIM * SDIM);
        k3_reward<<<dim3(BDIM / BM, RHDIM / BN), 256>>>(parn, W_r1, b_r1);
        k4_reduce<<<BDIM, 128>>>(parn, w_r2, b_r2, disc);
        disc *= 0.99f;
    }
    k_final<<<16, 256>>>(out);
}

// round 2
// speedup vs baseline: 2.1311x; 2.1311x over previous
#include <cuda_runtime.h>
#include <math.h>

// Problem constants
#define BDIM 4096   // trajectories
#define HDIM 1024   // GRU state
#define SDIM 256    // stochastic latent
#define NSAMP 256
#define TSTEPS 10
#define RHDIM 512   // reward hidden
#define N3 3072     // Wx/Wh leading dim (3*H)

// MMA tiling (all GEMMs): block 128x32, BK=32, 8 warps, warp = 16 rows x 32 cols
#define BM 128
#define BN 32
#define BK 32
#define BSTR 36     // smem row stride (pad 4) -> conflict-free frag loads

// Persistent scratch (allocation-free: __device__ globals)
__device__ float g_h[2][BDIM * HDIM];     // ping-pong GRU state
__device__ float g_s[BDIM * SDIM];        // stochastic latent
__device__ float g_relu[BDIM * RHDIM];    // reward hidden activations
__device__ float g_acc[BDIM];             // discounted (reward + epistemic) accumulator

__device__ __forceinline__ float sigm_(float x) { return 1.0f / (1.0f + expf(-x)); }
__device__ __forceinline__ float softplus_(float x) {
    return fmaxf(x, 0.0f) + log1pf(expf(-fabsf(x)));
}
__device__ __forceinline__ unsigned f2tf(float x) {
    unsigned u; asm("cvt.rna.tf32.f32 %0, %1;" : "=r"(u) : "f"(x)); return u;
}
__device__ __forceinline__ void cvt4(unsigned* d, float4 v) {
    d[0] = f2tf(v.x); d[1] = f2tf(v.y); d[2] = f2tf(v.z); d[3] = f2tf(v.w);
}
__device__ __forceinline__ void mma_tf32(float c[4], unsigned a0, unsigned a1,
                                         unsigned a2, unsigned a3,
                                         unsigned b0, unsigned b1) {
    asm volatile(
        "mma.sync.aligned.m16n8k8.row.col.f32.tf32.tf32.f32 "
        "{%0,%1,%2,%3},{%4,%5,%6,%7},{%8,%9},{%0,%1,%2,%3};\n"
        : "+f"(c[0]), "+f"(c[1]), "+f"(c[2]), "+f"(c[3])
        : "r"(a0), "r"(a1), "r"(a2), "r"(a3), "r"(b0), "r"(b1));
}

// ---------------------------------------------------------------------------
// init: broadcast h0/s0 to all B rows, zero accumulator
// ---------------------------------------------------------------------------
__global__ void k_init(const float* __restrict__ h0, const float* __restrict__ s0) {
    int idx = blockIdx.x * blockDim.x + threadIdx.x;
    int stride = gridDim.x * blockDim.x;
    for (int i = idx; i < BDIM * HDIM; i += stride) g_h[0][i] = h0[i & (HDIM - 1)];
    for (int i = idx; i < BDIM * SDIM; i += stride) g_s[i] = s0[i & (SDIM - 1)];
    for (int i = idx; i < BDIM; i += stride) g_acc[i] = 0.0f;
}

// ---------------------------------------------------------------------------
// K1: fused GRU gates GEMM (tf32 mma) + h update.
// u = [s(256), h(1024)], W = [Wx;Wh] (1280 x 3072), 3 gate column groups.
// n gate split at k=256 into x-part (accNX) and h-part (acc[2]).
// grid (32, 32), 256 threads.
// ---------------------------------------------------------------------------
__global__ __launch_bounds__(256)
void k1_gru(int par,
            const float* __restrict__ Wx, const float* __restrict__ Wh,
            const float* __restrict__ b_gru, const int* __restrict__ acts_t) {
    const float* __restrict__ h_in = g_h[par];
    float* __restrict__ h_out = g_h[par ^ 1];

    __shared__ unsigned As[BM][BSTR];        // 128x32 tf32 activations
    __shared__ unsigned Bs[3][BK][BSTR];     // 3 gates x 32k x 32n

    const int tid = threadIdx.x;
    const int lane = tid & 31;
    const int warp = tid >> 5;
    const int row0 = blockIdx.x * BM;
    const int col0 = blockIdx.y * BN;
    const int wr = warp * 16;

    float acc[3][4][4];   // [gate][ntile][reg]
    float accNX[4][4];
#pragma unroll
    for (int g = 0; g < 3; g++)
#pragma unroll
        for (int nt = 0; nt < 4; nt++)
#pragma unroll
            for (int r = 0; r < 4; r++) acc[g][nt][r] = 0.0f;

    const int KT_X = SDIM / BK;             // 8
    const int KT_ALL = KT_X + HDIM / BK;    // 40

#pragma unroll 1
    for (int kt = 0; kt < KT_ALL; ++kt) {
        if (kt == KT_X) {
#pragma unroll
            for (int nt = 0; nt < 4; nt++)
#pragma unroll
                for (int r = 0; r < 4; r++) { accNX[nt][r] = acc[2][nt][r]; acc[2][nt][r] = 0.0f; }
        }
        const bool xr = (kt < KT_X);
        const int k0 = xr ? kt * BK : (kt - KT_X) * BK;
        const float* abase = xr ? g_s : h_in;
        const int astride = xr ? SDIM : HDIM;

        // stage global loads
        float4 av[4];
#pragma unroll
        for (int i = 0; i < 4; i++) {
            int v = tid + 256 * i;
            int r = v >> 3, kv = (v & 7) * 4;
            av[i] = *(const float4*)(abase + (size_t)(row0 + r) * astride + k0 + kv);
        }
        const int bk = tid >> 3, bn4 = (tid & 7) * 4;
        const float* wb = (xr ? Wx : Wh) + (size_t)(k0 + bk) * N3 + col0 + bn4;
        float4 bv[3];
#pragma unroll
        for (int g = 0; g < 3; g++) bv[g] = *(const float4*)(wb + g * HDIM);

        __syncthreads();
#pragma unroll
        for (int i = 0; i < 4; i++) {
            int v = tid + 256 * i;
            int r = v >> 3, kv = (v & 7) * 4;
            cvt4(&As[r][kv], av[i]);
        }
#pragma unroll
        for (int g = 0; g < 3; g++) cvt4(&Bs[g][bk][bn4], bv[g]);
        __syncthreads();

#pragma unroll
        for (int kc = 0; kc < 4; ++kc) {
            const int kb = kc * 8;
            unsigned a0 = As[wr + (lane >> 2)][kb + (lane & 3)];
            unsigned a1 = As[wr + 8 + (lane >> 2)][kb + (lane & 3)];
            unsigned a2 = As[wr + (lane >> 2)][kb + (lane & 3) + 4];
            unsigned a3 = As[wr + 8 + (lane >> 2)][kb + (lane & 3) + 4];
#pragma unroll
            for (int g = 0; g < 3; g++) {
#pragma unroll
                for (int nt = 0; nt < 4; nt++) {
                    unsigned b0 = Bs[g][kb + (lane & 3)][nt * 8 + (lane >> 2)];
                    unsigned b1 = Bs[g][kb + (lane & 3) + 4][nt * 8 + (lane >> 2)];
                    mma_tf32(acc[g][nt], a0, a1, a2, a3, b0, b1);
                }
            }
        }
    }

    // epilogue: C(row, col) -> c[ri*2+cj] at row = wr + lane>>2 + 8*ri,
    // col = col0 + nt*8 + 2*(lane&3) + cj
#pragma unroll
    for (int ri = 0; ri < 2; ri++) {
        int b = row0 + wr + (lane >> 2) + ri * 8;
        int a = acts_t[b];
        const float* wa = Wx + (size_t)(SDIM + a) * N3;
#pragma unroll
        for (int nt = 0; nt < 4; nt++) {
#pragma unroll
            for (int cj = 0; cj < 2; cj++) {
                int c = col0 + nt * 8 + 2 * (lane & 3) + cj;
                int idx = ri * 2 + cj;
                float z = sigm_(acc[0][nt][idx] + wa[c] + b_gru[c]);
                float r = sigm_(acc[1][nt][idx] + wa[HDIM + c] + b_gru[HDIM + c]);
                float n = tanhf(accNX[nt][idx] + wa[2 * HDIM + c]
                                + r * acc[2][nt][idx] + b_gru[2 * HDIM + c]);
                float hp = h_in[(size_t)b * HDIM + c];
                h_out[(size_t)b * HDIM + c] = (1.0f - z) * hp + z * n;
            }
        }
    }
}

// ---------------------------------------------------------------------------
// K2: mu/std GEMM (tf32 mma, K=1024, N=256) + latent sample.
// grid (32, 8), 256 threads.
// ---------------------------------------------------------------------------
__global__ __launch_bounds__(256)
void k2_latent(int parn,
               const float* __restrict__ W_mu, const float* __restrict__ b_mu,
               const float* __restrict__ W_std, const float* __restrict__ b_std,
               const float* __restrict__ noise_t) {
    const float* __restrict__ h_new = g_h[parn];

    __shared__ unsigned As[BM][BSTR];
    __shared__ unsigned Bs[2][BK][BSTR];

    const int tid = threadIdx.x;
    const int lane = tid & 31;
    const int warp = tid >> 5;
    const int row0 = blockIdx.x * BM;
    const int col0 = blockIdx.y * BN;
    const int wr = warp * 16;

    float acc[2][4][4];
#pragma unroll
    for (int g = 0; g < 2; g++)
#pragma unroll
        for (int nt = 0; nt < 4; nt++)
#pragma unroll
            for (int r = 0; r < 4; r++) acc[g][nt][r] = 0.0f;

#pragma unroll 1
    for (int kt = 0; kt < HDIM / BK; ++kt) {
        const int k0 = kt * BK;

        float4 av[4];
#pragma unroll
        for (int i = 0; i < 4; i++) {
            int v = tid + 256 * i;
            int r = v >> 3, kv = (v & 7) * 4;
            av[i] = *(const float4*)(h_new + (size_t)(row0 + r) * HDIM + k0 + kv);
        }
        const int bk = tid >> 3, bn4 = (tid & 7) * 4;
        float4 bm = *(const float4*)(W_mu + (size_t)(k0 + bk) * SDIM + col0 + bn4);
        float4 bs = *(const float4*)(W_std + (size_t)(k0 + bk) * SDIM + col0 + bn4);

        __syncthreads();
#pragma unroll
        for (int i = 0; i < 4; i++) {
            int v = tid + 256 * i;
            int r = v >> 3, kv = (v & 7) * 4;
            cvt4(&As[r][kv], av[i]);
        }
        cvt4(&Bs[0][bk][bn4], bm);
        cvt4(&Bs[1][bk][bn4], bs);
        __syncthreads();

#pragma unroll
        for (int kc = 0; kc < 4; ++kc) {
            const int kb = kc * 8;
            unsigned a0 = As[wr + (lane >> 2)][kb + (lane & 3)];
            unsigned a1 = As[wr + 8 + (lane >> 2)][kb + (lane & 3)];
            unsigned a2 = As[wr + (lane >> 2)][kb + (lane & 3) + 4];
            unsigned a3 = As[wr + 8 + (lane >> 2)][kb + (lane & 3) + 4];
#pragma unroll
            for (int g = 0; g < 2; g++) {
#pragma unroll
                for (int nt = 0; nt < 4; nt++) {
                    unsigned b0 = Bs[g][kb + (lane & 3)][nt * 8 + (lane >> 2)];
                    unsigned b1 = Bs[g][kb + (lane & 3) + 4][nt * 8 + (lane >> 2)];
                    mma_tf32(acc[g][nt], a0, a1, a2, a3, b0, b1);
                }
            }
        }
    }

#pragma unroll
    for (int ri = 0; ri < 2; ri++) {
        int b = row0 + wr + (lane >> 2) + ri * 8;
#pragma unroll
        for (int nt = 0; nt < 4; nt++) {
#pragma unroll
            for (int cj = 0; cj < 2; cj++) {
                int c = col0 + nt * 8 + 2 * (lane & 3) + cj;
                int idx = ri * 2 + cj;
                float mu = acc[0][nt][idx] + b_mu[c];
                float sl = acc[1][nt][idx] + b_std[c];
                float sd = softplus_(sl) + 0.1f;
                g_s[(size_t)b * SDIM + c] = mu + sd * noise_t[(size_t)b * SDIM + c];
            }
        }
    }
}

// ---------------------------------------------------------------------------
// K3: reward hidden GEMM (tf32 mma, K=1280 split at 1024, N=512) + ReLU.
// grid (32, 16), 256 threads.
// ---------------------------------------------------------------------------
__global__ __launch_bounds__(256)
void k3_reward(int parn, const float* __restrict__ W_r1, const float* __restrict__ b_r1) {
    const float* __restrict__ h_new = g_h[parn];

    __shared__ unsigned As[BM][BSTR];
    __shared__ unsigned Bs[BK][BSTR];

    const int tid = threadIdx.x;
    const int lane = tid & 31;
    const int warp = tid >> 5;
    const int row0 = blockIdx.x * BM;
    const int col0 = blockIdx.y * BN;
    const int wr = warp * 16;

    float acc[4][4];
#pragma unroll
    for (int nt = 0; nt < 4; nt++)
#pragma unroll
        for (int r = 0; r < 4; r++) acc[nt][r] = 0.0f;

    const int KT_H = HDIM / BK;            // 32
    const int KT_ALL = KT_H + SDIM / BK;   // 40

#pragma unroll 1
    for (int kt = 0; kt < KT_ALL; ++kt) {
        const bool hr = (kt < KT_H);
        const int k0 = hr ? kt * BK : (kt - KT_H) * BK;
        const int kglob = hr ? k0 : (HDIM + k0);
        const float* abase = hr ? h_new : g_s;
        const int astride = hr ? HDIM : SDIM;

        float4 av[4];
#pragma unroll
        for (int i = 0; i < 4; i++) {
            int v = tid + 256 * i;
            int r = v >> 3, kv = (v & 7) * 4;
            av[i] = *(const float4*)(abase + (size_t)(row0 + r) * astride + k0 + kv);
        }
        const int bk = tid >> 3, bn4 = (tid & 7) * 4;
        float4 bw = *(const float4*)(W_r1 + (size_t)(kglob + bk) * RHDIM + col0 + bn4);

        __syncthreads();
#pragma unroll
        for (int i = 0; i < 4; i++) {
            int v = tid + 256 * i;
            int r = v >> 3, kv = (v & 7) * 4;
            cvt4(&As[r][kv], av[i]);
        }
        cvt4(&Bs[bk][bn4], bw);
        __syncthreads();

#pragma unroll
        for (int kc = 0; kc < 4; ++kc) {
            const int kb = kc * 8;
            unsigned a0 = As[wr + (lane >> 2)][kb + (lane & 3)];
            unsigned a1 = As[wr + 8 + (lane >> 2)][kb + (lane & 3)];
            unsigned a2 = As[wr + (lane >> 2)][kb + (lane & 3) + 4];
            unsigned a3 = As[wr + 8 + (lane >> 2)][kb + (lane & 3) + 4];
#pragma unroll
            for (int nt = 0; nt < 4; nt++) {
                unsigned b0 = Bs[kb + (lane & 3)][nt * 8 + (lane >> 2)];
                unsigned b1 = Bs[kb + (lane & 3) + 4][nt * 8 + (lane >> 2)];
                mma_tf32(acc[nt], a0, a1, a2, a3, b0, b1);
            }
        }
    }

#pragma unroll
    for (int ri = 0; ri < 2; ri++) {
        int b = row0 + wr + (lane >> 2) + ri * 8;
#pragma unroll
        for (int nt = 0; nt < 4; nt++) {
#pragma unroll
            for (int cj = 0; cj < 2; cj++) {
                int c = col0 + nt * 8 + 2 * (lane & 3) + cj;
                int idx = ri * 2 + cj;
                g_relu[(size_t)b * RHDIM + c] = fmaxf(acc[nt][idx] + b_r1[c], 0.0f);
            }
        }
    }
}

// ---------------------------------------------------------------------------
// K4: per-row reduction. reward = relu_row . w_r2 + b_r2; var(feat);
//     g_acc[b] += disc * (reward + var).
// ---------------------------------------------------------------------------
__global__ void k4_reduce(int parn, const float* __restrict__ w_r2,
                          const float* __restrict__ b_r2, float disc) {
    const int b = blockIdx.x;
    const int tid = threadIdx.x;
    const float* __restrict__ hr = g_h[parn] + (size_t)b * HDIM;
    const float* __restrict__ sr = g_s + (size_t)b * SDIM;
    const float* __restrict__ rr = g_relu + (size_t)b * RHDIM;

    float sum = 0.0f, sq = 0.0f, dot = 0.0f;
    for (int k = tid; k < HDIM; k += 128) { float v = hr[k]; sum += v; sq = fmaf(v, v, sq); }
    for (int k = tid; k < SDIM; k += 128) { float v = sr[k]; sum += v; sq = fmaf(v, v, sq); }
    for (int k = tid; k < RHDIM; k += 128) dot = fmaf(rr[k], w_r2[k], dot);

#pragma unroll
    for (int off = 16; off > 0; off >>= 1) {
        sum += __shfl_down_sync(0xffffffffu, sum, off);
        sq  += __shfl_down_sync(0xffffffffu, sq, off);
        dot += __shfl_down_sync(0xffffffffu, dot, off);
    }
    __shared__ float s1[4], s2[4], s3[4];
    if ((tid & 31) == 0) { s1[tid >> 5] = sum; s2[tid >> 5] = sq; s3[tid >> 5] = dot; }
    __syncthreads();
    if (tid == 0) {
        float S = s1[0] + s1[1] + s1[2] + s1[3];
        float Q = s2[0] + s2[1] + s2[2] + s2[3];
        float D = s3[0] + s3[1] + s3[2] + s3[3];
        float mean = S * (1.0f / 1280.0f);
        float var = Q * (1.0f / 1280.0f) - mean * mean;
        float reward = D + b_r2[0];
        g_acc[b] += disc * (reward + var);
    }
}

// ---------------------------------------------------------------------------
// final: out[a] = -mean over 256 samples of g_acc
// ---------------------------------------------------------------------------
__global__ void k_final(float* __restrict__ out) {
    const int a = blockIdx.x;
    const int tid = threadIdx.x;  // 256 threads
    float v = g_acc[a * NSAMP + tid];
#pragma unroll
    for (int off = 16; off > 0; off >>= 1) v += __shfl_down_sync(0xffffffffu, v, off);
    __shared__ float w[8];
    if ((tid & 31) == 0) w[tid >> 5] = v;
    __syncthreads();
    if (tid < 8) {
        float x = w[tid];
#pragma unroll
        for (int off = 4; off > 0; off >>= 1) x += __shfl_down_sync(0xffu, x, off);
        if (tid == 0) out[a] = -x * (1.0f / (float)NSAMP);
    }
}

// ---------------------------------------------------------------------------
extern "C" void kernel_launch(void* const* d_in, const int* in_sizes, int n_in,
                              void* d_out, int out_size) {
    (void)in_sizes; (void)n_in; (void)out_size;
    const float* h0    = (const float*)d_in[0];
    const float* s0    = (const float*)d_in[1];
    const float* noise = (const float*)d_in[2];
    const float* Wx    = (const float*)d_in[3];
    const float* Wh    = (const float*)d_in[4];
    const float* b_gru = (const float*)d_in[5];
    const float* W_mu  = (const float*)d_in[6];
    const float* b_mu  = (const float*)d_in[7];
    const float* W_std = (const float*)d_in[8];
    const float* b_std = (const float*)d_in[9];
    const float* W_r1  = (const float*)d_in[10];
    const float* b_r1  = (const float*)d_in[11];
    const float* w_r2  = (const float*)d_in[12];
    const float* b_r2  = (const float*)d_in[13];
    const int*   acts  = (const int*)d_in[14];
    float* out = (float*)d_out;

    k_init<<<512, 256>>>(h0, s0);

    float disc = 1.0f;
    for (int t = 0; t < TSTEPS; ++t) {
        int par = t & 1;
        int parn = par ^ 1;
        k1_gru<<<dim3(BDIM / BM, HDIM / BN), 256>>>(par, Wx, Wh, b_gru, acts + (size_t)t * BDIM);
        k2_latent<<<dim3(BDIM / BM, SDIM / BN), 256>>>(parn, W_mu, b_mu, W_std, b_std,
                                                       noise + (size_t)t * BDIM * SDIM);
        k3_reward<<<dim3(BDIM / BM, RHDIM / BN), 256>>>(parn, W_r1, b_r1);
        k4_reduce<<<BDIM, 128>>>(parn, w_r2, b_r2, disc);
        disc *= 0.99f;
    }
    k_final<<<16, 256>>>(out);
}

// round 4
// speedup vs baseline: 3.6726x; 1.7234x over previous
#include <cuda_runtime.h>
#include <math.h>
#include <cstdint>

// Problem constants
#define BDIM 4096
#define HDIM 1024
#define SDIM 256
#define NSAMP 256
#define TSTEPS 10
#define RHDIM 512
#define N3 3072

#define BM 128
#define BN 32
#define BK 32
#define ABASE 12288          // 3 stages * 4096 words of A
#define ASTG 4096            // A words per stage (128*32, xor-swizzled, no pad)
#define BROW 40              // B smem row stride (pad 32->40), conflict-free

// Persistent scratch
__device__ float g_h[2][BDIM * HDIM];
__device__ float g_s[BDIM * SDIM];
__device__ float g_relu[BDIM * RHDIM];
__device__ float g_acc[BDIM];
// Pre-permuted tf32 weights (fragment-ready layout)
__device__ float W1p[32 * 40 * 3 * 1024];   // [cb][kt][g][k][32]
__device__ float W2p[8 * 32 * 2 * 1024];    // [cb][kt][g][k][32]
__device__ float W3p[16 * 40 * 1024];       // [cb][kt][k][32]

__device__ __forceinline__ float sigm_(float x) { return 1.0f / (1.0f + expf(-x)); }
__device__ __forceinline__ float softplus_(float x) {
    return fmaxf(x, 0.0f) + log1pf(expf(-fabsf(x)));
}
__device__ __forceinline__ float f2tf(float x) {
    unsigned u; asm("cvt.rna.tf32.f32 %0, %1;" : "=r"(u) : "f"(x));
    return __uint_as_float(u);
}
__device__ __forceinline__ void mma_tf32(float c[4], float a0, float a1, float a2, float a3,
                                         float b0, float b1) {
    asm volatile(
        "mma.sync.aligned.m16n8k8.row.col.f32.tf32.tf32.f32 "
        "{%0,%1,%2,%3},{%4,%5,%6,%7},{%8,%9},{%0,%1,%2,%3};\n"
        : "+f"(c[0]), "+f"(c[1]), "+f"(c[2]), "+f"(c[3])
        : "r"(__float_as_uint(a0)), "r"(__float_as_uint(a1)),
          "r"(__float_as_uint(a2)), "r"(__float_as_uint(a3)),
          "r"(__float_as_uint(b0)), "r"(__float_as_uint(b1)));
}
__device__ __forceinline__ void cp16(uint32_t dst, const float* src) {
    asm volatile("cp.async.cg.shared.global [%0], [%1], 16;" :: "r"(dst), "l"(src));
}
__device__ __forceinline__ void cp_commit() { asm volatile("cp.async.commit_group;"); }
template<int N> __device__ __forceinline__ void cp_wait() {
    asm volatile("cp.async.wait_group %0;" :: "n"(N));
}

// ---------------------------------------------------------------------------
// init + weight permutation
// ---------------------------------------------------------------------------
__global__ void k_init(const float* __restrict__ h0, const float* __restrict__ s0) {
    int idx = blockIdx.x * blockDim.x + threadIdx.x;
    int stride = gridDim.x * blockDim.x;
    for (int i = idx; i < BDIM * HDIM; i += stride) g_h[0][i] = h0[i & (HDIM - 1)];
    for (int i = idx; i < BDIM * SDIM; i += stride) g_s[i] = s0[i & (SDIM - 1)];
    for (int i = idx; i < BDIM; i += stride) g_acc[i] = 0.0f;
}

// dst[cb][kt][g][k][p], p = c8*4+nt where src col = nt*8+c8
__global__ void k_prep1(const float* __restrict__ Wx, const float* __restrict__ Wh) {
    const int total = 32 * 40 * 3 * 1024;
    for (int idx = blockIdx.x * blockDim.x + threadIdx.x; idx < total;
         idx += gridDim.x * blockDim.x) {
        int p = idx & 31, k = (idx >> 5) & 31;
        int rest = idx >> 10;
        int g = rest % 3; rest /= 3;
        int kt = rest % 40; int cb = rest / 40;
        int c = (p & 3) * 8 + (p >> 2);
        int row = kt * 32 + k;
        float v = (row < 256) ? Wx[(size_t)row * N3 + g * HDIM + cb * 32 + c]
                              : Wh[(size_t)(row - 256) * N3 + g * HDIM + cb * 32 + c];
        W1p[idx] = f2tf(v);
    }
}
__global__ void k_prep2(const float* __restrict__ W_mu, const float* __restrict__ W_std) {
    const int total = 8 * 32 * 2 * 1024;
    for (int idx = blockIdx.x * blockDim.x + threadIdx.x; idx < total;
         idx += gridDim.x * blockDim.x) {
        int p = idx & 31, k = (idx >> 5) & 31;
        int rest = idx >> 10;
        int g = rest & 1; rest >>= 1;
        int kt = rest & 31; int cb = rest >> 5;
        int c = (p & 3) * 8 + (p >> 2);
        const float* W = g ? W_std : W_mu;
        W2p[idx] = f2tf(W[(size_t)(kt * 32 + k) * SDIM + cb * 32 + c]);
    }
}
__global__ void k_prep3(const float* __restrict__ W_r1) {
    const int total = 16 * 40 * 1024;
    for (int idx = blockIdx.x * blockDim.x + threadIdx.x; idx < total;
         idx += gridDim.x * blockDim.x) {
        int p = idx & 31, k = (idx >> 5) & 31;
        int rest = idx >> 10;
        int kt = rest % 40; int cb = rest / 40;
        int c = (p & 3) * 8 + (p >> 2);
        W3p[idx] = f2tf(W_r1[(size_t)(kt * 32 + k) * RHDIM + cb * 32 + c]);
    }
}

// ---------------------------------------------------------------------------
// K1: GRU gates GEMM, cp.async 3-stage pipeline, tf32 mma. grid (32,32).
// ---------------------------------------------------------------------------
__global__ __launch_bounds__(256, 2)
void k1_gru(int par, const float* __restrict__ Wx,
            const float* __restrict__ b_gru, const int* __restrict__ acts_t) {
    extern __shared__ float smem[];
    const float* __restrict__ h_in = g_h[par];
    float* __restrict__ h_out = g_h[par ^ 1];

    const int tid = threadIdx.x, lane = tid & 31, warp = tid >> 5;
    const int row0 = blockIdx.x * BM, col0 = blockIdx.y * BN;
    const int wr = warp * 16;
    const uint32_t smem_b = (uint32_t)__cvta_generic_to_shared(smem);

    // cp.async A: 4 chunks/thread. r = rbase + 32i, c4 = tid&7
    const int c4 = tid & 7, rbase = tid >> 3, rx0 = rbase & 7;
    int dstAw[4];
#pragma unroll
    for (int i = 0; i < 4; i++) dstAw[i] = (rbase + 32 * i) * 32 + (c4 ^ rx0) * 4;
    const float* sA = g_s + (size_t)(row0 + rbase) * SDIM + c4 * 4;
    const float* hA = h_in + (size_t)(row0 + rbase) * HDIM + c4 * 4;
    // cp.async B: 3 chunks/thread (one per gate)
    const int bk = tid >> 3;  // 0..31
    const int dstBw = ABASE + bk * BROW + c4 * 4;
    const float* wblk = W1p + (size_t)blockIdx.y * (40 * 3 * 1024) + bk * 32 + c4 * 4;

#define K1_ISSUE(kt, s) do {                                                  \
    const float* ap; int astr;                                                \
    if ((kt) < 8) { ap = sA + (kt) * 32; astr = SDIM; }                       \
    else { ap = hA + ((kt) - 8) * 32; astr = HDIM; }                          \
    _Pragma("unroll")                                                         \
    for (int i = 0; i < 4; i++)                                               \
        cp16(smem_b + 4 * ((s) * ASTG + dstAw[i]), ap + (size_t)(32 * i) * astr); \
    const float* wp = wblk + (size_t)(kt) * 3072;                             \
    _Pragma("unroll")                                                         \
    for (int g = 0; g < 3; g++)                                               \
        cp16(smem_b + 4 * (3 * ASTG + (s) * 3840 + (dstBw - ABASE) + g * 1280), wp + g * 1024); \
    cp_commit(); } while (0)

    float acc[3][4][4], accNX[4][4];
#pragma unroll
    for (int g = 0; g < 3; g++)
#pragma unroll
        for (int nt = 0; nt < 4; nt++)
#pragma unroll
            for (int r = 0; r < 4; r++) acc[g][nt][r] = 0.0f;

    const int q = lane >> 2, klo = lane & 3;
    const int r1 = wr + q;
    const int rx = r1 & 7;
    const int r1w = r1 * 32 + klo, r2w = (r1 + 8) * 32 + klo;
    const int bfr = klo * BROW + q * 4;  // B fragment base (within gate)

    K1_ISSUE(0, 0);
    K1_ISSUE(1, 1);

    const int KT = 40;
#pragma unroll 1
    for (int kt = 0; kt < KT; ++kt) {
        if (kt + 1 < KT) cp_wait<1>(); else cp_wait<0>();
        __syncthreads();
        if (kt + 2 < KT) K1_ISSUE(kt + 2, (kt + 2) % 3);

        if (kt == 8) {
#pragma unroll
            for (int nt = 0; nt < 4; nt++)
#pragma unroll
                for (int r = 0; r < 4; r++) { accNX[nt][r] = acc[2][nt][r]; acc[2][nt][r] = 0.0f; }
        }
        const int sA_ = (kt % 3) * ASTG;
        const int sB_ = ABASE + (kt % 3) * 3840;
#pragma unroll
        for (int kc = 0; kc < 4; ++kc) {
            float a0 = smem[sA_ + r1w + ((2 * kc) ^ rx) * 4];
            float a1 = smem[sA_ + r2w + ((2 * kc) ^ rx) * 4];
            float a2 = smem[sA_ + r1w + ((2 * kc + 1) ^ rx) * 4];
            float a3 = smem[sA_ + r2w + ((2 * kc + 1) ^ rx) * 4];
#pragma unroll
            for (int g = 0; g < 3; g++) {
                const int bb = sB_ + g * 1280 + kc * 8 * BROW + bfr;
                float4 b0 = *(const float4*)&smem[bb];
                float4 b1 = *(const float4*)&smem[bb + 4 * BROW];
                mma_tf32(acc[g][0], a0, a1, a2, a3, b0.x, b1.x);
                mma_tf32(acc[g][1], a0, a1, a2, a3, b0.y, b1.y);
                mma_tf32(acc[g][2], a0, a1, a2, a3, b0.z, b1.z);
                mma_tf32(acc[g][3], a0, a1, a2, a3, b0.w, b1.w);
            }
        }
    }
#undef K1_ISSUE

#pragma unroll
    for (int ri = 0; ri < 2; ri++) {
        int b = row0 + r1 + ri * 8;
        int a = acts_t[b];
        const float* wa = Wx + (size_t)(SDIM + a) * N3;
#pragma unroll
        for (int nt = 0; nt < 4; nt++) {
#pragma unroll
            for (int cj = 0; cj < 2; cj++) {
                int c = col0 + nt * 8 + 2 * klo + cj;
                int idx = ri * 2 + cj;
                float z = sigm_(acc[0][nt][idx] + wa[c] + b_gru[c]);
                float r = sigm_(acc[1][nt][idx] + wa[HDIM + c] + b_gru[HDIM + c]);
                float n = tanhf(accNX[nt][idx] + wa[2 * HDIM + c]
                                + r * acc[2][nt][idx] + b_gru[2 * HDIM + c]);
                float hp = h_in[(size_t)b * HDIM + c];
                h_out[(size_t)b * HDIM + c] = (1.0f - z) * hp + z * n;
            }
        }
    }
}

// ---------------------------------------------------------------------------
// K2: mu/std GEMM + latent sample. grid (32,8).
// ---------------------------------------------------------------------------
__global__ __launch_bounds__(256, 2)
void k2_latent(int parn, const float* __restrict__ b_mu, const float* __restrict__ b_std,
               const float* __restrict__ noise_t) {
    extern __shared__ float smem[];
    const float* __restrict__ h_new = g_h[parn];

    const int tid = threadIdx.x, lane = tid & 31, warp = tid >> 5;
    const int row0 = blockIdx.x * BM, col0 = blockIdx.y * BN;
    const int wr = warp * 16;
    const uint32_t smem_b = (uint32_t)__cvta_generic_to_shared(smem);

    const int c4 = tid & 7, rbase = tid >> 3, rx0 = rbase & 7;
    int dstAw[4];
#pragma unroll
    for (int i = 0; i < 4; i++) dstAw[i] = (rbase + 32 * i) * 32 + (c4 ^ rx0) * 4;
    const float* hA = h_new + (size_t)(row0 + rbase) * HDIM + c4 * 4;
    const int bk = tid >> 3;
    const int dstBw = bk * BROW + c4 * 4;
    const float* wblk = W2p + (size_t)blockIdx.y * (32 * 2 * 1024) + bk * 32 + c4 * 4;

#define K2_ISSUE(kt, s) do {                                                  \
    const float* ap = hA + (kt) * 32;                                         \
    _Pragma("unroll")                                                         \
    for (int i = 0; i < 4; i++)                                               \
        cp16(smem_b + 4 * ((s) * ASTG + dstAw[i]), ap + (size_t)(32 * i) * HDIM); \
    const float* wp = wblk + (size_t)(kt) * 2048;                             \
    _Pragma("unroll")                                                         \
    for (int g = 0; g < 2; g++)                                               \
        cp16(smem_b + 4 * (3 * ASTG + (s) * 2560 + dstBw + g * 1280), wp + g * 1024); \
    cp_commit(); } while (0)

    float acc[2][4][4];
#pragma unroll
    for (int g = 0; g < 2; g++)
#pragma unroll
        for (int nt = 0; nt < 4; nt++)
#pragma unroll
            for (int r = 0; r < 4; r++) acc[g][nt][r] = 0.0f;

    const int q = lane >> 2, klo = lane & 3;
    const int r1 = wr + q;
    const int rx = r1 & 7;
    const int r1w = r1 * 32 + klo, r2w = (r1 + 8) * 32 + klo;
    const int bfr = klo * BROW + q * 4;

    K2_ISSUE(0, 0);
    K2_ISSUE(1, 1);

    const int KT = 32;
#pragma unroll 1
    for (int kt = 0; kt < KT; ++kt) {
        if (kt + 1 < KT) cp_wait<1>(); else cp_wait<0>();
        __syncthreads();
        if (kt + 2 < KT) K2_ISSUE(kt + 2, (kt + 2) % 3);

        const int sA_ = (kt % 3) * ASTG;
        const int sB_ = ABASE + (kt % 3) * 2560;
#pragma unroll
        for (int kc = 0; kc < 4; ++kc) {
            float a0 = smem[sA_ + r1w + ((2 * kc) ^ rx) * 4];
            float a1 = smem[sA_ + r2w + ((2 * kc) ^ rx) * 4];
            float a2 = smem[sA_ + r1w + ((2 * kc + 1) ^ rx) * 4];
            float a3 = smem[sA_ + r2w + ((2 * kc + 1) ^ rx) * 4];
#pragma unroll
            for (int g = 0; g < 2; g++) {
                const int bb = sB_ + g * 1280 + kc * 8 * BROW + bfr;
                float4 b0 = *(const float4*)&smem[bb];
                float4 b1 = *(const float4*)&smem[bb + 4 * BROW];
                mma_tf32(acc[g][0], a0, a1, a2, a3, b0.x, b1.x);
                mma_tf32(acc[g][1], a0, a1, a2, a3, b0.y, b1.y);
                mma_tf32(acc[g][2], a0, a1, a2, a3, b0.z, b1.z);
                mma_tf32(acc[g][3], a0, a1, a2, a3, b0.w, b1.w);
            }
        }
    }
#undef K2_ISSUE

#pragma unroll
    for (int ri = 0; ri < 2; ri++) {
        int b = row0 + r1 + ri * 8;
#pragma unroll
        for (int nt = 0; nt < 4; nt++) {
#pragma unroll
            for (int cj = 0; cj < 2; cj++) {
                int c = col0 + nt * 8 + 2 * klo + cj;
                int idx = ri * 2 + cj;
                float mu = acc[0][nt][idx] + b_mu[c];
                float sd = softplus_(acc[1][nt][idx] + b_std[c]) + 0.1f;
                g_s[(size_t)b * SDIM + c] = mu + sd * noise_t[(size_t)b * SDIM + c];
            }
        }
    }
}

// ---------------------------------------------------------------------------
// K3: reward hidden GEMM + ReLU. grid (32,16). K=1280 split at 1024.
// ---------------------------------------------------------------------------
__global__ __launch_bounds__(256, 2)
void k3_reward(int parn, const float* __restrict__ b_r1) {
    extern __shared__ float smem[];
    const float* __restrict__ h_new = g_h[parn];

    const int tid = threadIdx.x, lane = tid & 31, warp = tid >> 5;
    const int row0 = blockIdx.x * BM, col0 = blockIdx.y * BN;
    const int wr = warp * 16;
    const uint32_t smem_b = (uint32_t)__cvta_generic_to_shared(smem);

    const int c4 = tid & 7, rbase = tid >> 3, rx0 = rbase & 7;
    int dstAw[4];
#pragma unroll
    for (int i = 0; i < 4; i++) dstAw[i] = (rbase + 32 * i) * 32 + (c4 ^ rx0) * 4;
    const float* hA = h_new + (size_t)(row0 + rbase) * HDIM + c4 * 4;
    const float* sA = g_s + (size_t)(row0 + rbase) * SDIM + c4 * 4;
    const int bk = tid >> 3;
    const int dstBw = bk * BROW + c4 * 4;
    const float* wblk = W3p + (size_t)blockIdx.y * (40 * 1024) + bk * 32 + c4 * 4;

#define K3_ISSUE(kt, s) do {                                                  \
    const float* ap; int astr;                                                \
    if ((kt) < 32) { ap = hA + (kt) * 32; astr = HDIM; }                      \
    else { ap = sA + ((kt) - 32) * 32; astr = SDIM; }                         \
    _Pragma("unroll")                                                         \
    for (int i = 0; i < 4; i++)                                               \
        cp16(smem_b + 4 * ((s) * ASTG + dstAw[i]), ap + (size_t)(32 * i) * astr); \
    cp16(smem_b + 4 * (3 * ASTG + (s) * 1280 + dstBw), wblk + (size_t)(kt) * 1024); \
    cp_commit(); } while (0)

    float acc[4][4];
#pragma unroll
    for (int nt = 0; nt < 4; nt++)
#pragma unroll
        for (int r = 0; r < 4; r++) acc[nt][r] = 0.0f;

    const int q = lane >> 2, klo = lane & 3;
    const int r1 = wr + q;
    const int rx = r1 & 7;
    const int r1w = r1 * 32 + klo, r2w = (r1 + 8) * 32 + klo;
    const int bfr = klo * BROW + q * 4;

    K3_ISSUE(0, 0);
    K3_ISSUE(1, 1);

    const int KT = 40;
#pragma unroll 1
    for (int kt = 0; kt < KT; ++kt) {
        if (kt + 1 < KT) cp_wait<1>(); else cp_wait<0>();
        __syncthreads();
        if (kt + 2 < KT) K3_ISSUE(kt + 2, (kt + 2) % 3);

        const int sA_ = (kt % 3) * ASTG;
        const int sB_ = ABASE + (kt % 3) * 1280;
#pragma unroll
        for (int kc = 0; kc < 4; ++kc) {
            float a0 = smem[sA_ + r1w + ((2 * kc) ^ rx) * 4];
            float a1 = smem[sA_ + r2w + ((2 * kc) ^ rx) * 4];
            float a2 = smem[sA_ + r1w + ((2 * kc + 1) ^ rx) * 4];
            float a3 = smem[sA_ + r2w + ((2 * kc + 1) ^ rx) * 4];
            const int bb = sB_ + kc * 8 * BROW + bfr;
            float4 b0 = *(const float4*)&smem[bb];
            float4 b1 = *(const float4*)&smem[bb + 4 * BROW];
            mma_tf32(acc[0], a0, a1, a2, a3, b0.x, b1.x);
            mma_tf32(acc[1], a0, a1, a2, a3, b0.y, b1.y);
            mma_tf32(acc[2], a0, a1, a2, a3, b0.z, b1.z);
            mma_tf32(acc[3], a0, a1, a2, a3, b0.w, b1.w);
        }
    }
#undef K3_ISSUE

#pragma unroll
    for (int ri = 0; ri < 2; ri++) {
        int b = row0 + r1 + ri * 8;
#pragma unroll
        for (int nt = 0; nt < 4; nt++) {
#pragma unroll
            for (int cj = 0; cj < 2; cj++) {
                int c = col0 + nt * 8 + 2 * klo + cj;
                int idx = ri * 2 + cj;
                g_relu[(size_t)b * RHDIM + c] = fmaxf(acc[nt][idx] + b_r1[c], 0.0f);
            }
        }
    }
}

// ---------------------------------------------------------------------------
// K4 + final reductions (unchanged)
// ---------------------------------------------------------------------------
__global__ void k4_reduce(int parn, const float* __restrict__ w_r2,
                          const float* __restrict__ b_r2, float disc) {
    const int b = blockIdx.x;
    const int tid = threadIdx.x;
    const float* __restrict__ hr = g_h[parn] + (size_t)b * HDIM;
    const float* __restrict__ sr = g_s + (size_t)b * SDIM;
    const float* __restrict__ rr = g_relu + (size_t)b * RHDIM;

    float sum = 0.0f, sq = 0.0f, dot = 0.0f;
    for (int k = tid; k < HDIM; k += 128) { float v = hr[k]; sum += v; sq = fmaf(v, v, sq); }
    for (int k = tid; k < SDIM; k += 128) { float v = sr[k]; sum += v; sq = fmaf(v, v, sq); }
    for (int k = tid; k < RHDIM; k += 128) dot = fmaf(rr[k], w_r2[k], dot);

#pragma unroll
    for (int off = 16; off > 0; off >>= 1) {
        sum += __shfl_down_sync(0xffffffffu, sum, off);
        sq  += __shfl_down_sync(0xffffffffu, sq, off);
        dot += __shfl_down_sync(0xffffffffu, dot, off);
    }
    __shared__ float s1[4], s2[4], s3[4];
    if ((tid & 31) == 0) { s1[tid >> 5] = sum; s2[tid >> 5] = sq; s3[tid >> 5] = dot; }
    __syncthreads();
    if (tid == 0) {
        float S = s1[0] + s1[1] + s1[2] + s1[3];
        float Q = s2[0] + s2[1] + s2[2] + s2[3];
        float D = s3[0] + s3[1] + s3[2] + s3[3];
        float mean = S * (1.0f / 1280.0f);
        float var = Q * (1.0f / 1280.0f) - mean * mean;
        g_acc[b] += disc * ((D + b_r2[0]) + var);
    }
}

__global__ void k_final(float* __restrict__ out) {
    const int a = blockIdx.x;
    const int tid = threadIdx.x;
    float v = g_acc[a * NSAMP + tid];
#pragma unroll
    for (int off = 16; off > 0; off >>= 1) v += __shfl_down_sync(0xffffffffu, v, off);
    __shared__ float w[8];
    if ((tid & 31) == 0) w[tid >> 5] = v;
    __syncthreads();
    if (tid < 8) {
        float x = w[tid];
#pragma unroll
        for (int off = 4; off > 0; off >>= 1) x += __shfl_down_sync(0xffu, x, off);
        if (tid == 0) out[a] = -x * (1.0f / (float)NSAMP);
    }
}

// ---------------------------------------------------------------------------
extern "C" void kernel_launch(void* const* d_in, const int* in_sizes, int n_in,
                              void* d_out, int out_size) {
    (void)in_sizes; (void)n_in; (void)out_size;
    const float* h0    = (const float*)d_in[0];
    const float* s0    = (const float*)d_in[1];
    const float* noise = (const float*)d_in[2];
    const float* Wx    = (const float*)d_in[3];
    const float* Wh    = (const float*)d_in[4];
    const float* b_gru = (const float*)d_in[5];
    const float* W_mu  = (const float*)d_in[6];
    const float* b_mu  = (const float*)d_in[7];
    const float* W_std = (const float*)d_in[8];
    const float* b_std = (const float*)d_in[9];
    const float* W_r1  = (const float*)d_in[10];
    const float* b_r1  = (const float*)d_in[11];
    const float* w_r2  = (const float*)d_in[12];
    const float* b_r2  = (const float*)d_in[13];
    const int*   acts  = (const int*)d_in[14];
    float* out = (float*)d_out;

    const int SM1 = (ABASE + 3 * 3840) * 4;   // 95232 B
    const int SM2 = (ABASE + 3 * 2560) * 4;   // 79872 B
    const int SM3 = (ABASE + 3 * 1280) * 4;   // 64512 B
    cudaFuncSetAttribute(k1_gru, cudaFuncAttributeMaxDynamicSharedMemorySize, SM1);
    cudaFuncSetAttribute(k2_latent, cudaFuncAttributeMaxDynamicSharedMemorySize, SM2);
    cudaFuncSetAttribute(k3_reward, cudaFuncAttributeMaxDynamicSharedMemorySize, SM3);

    k_init<<<512, 256>>>(h0, s0);
    k_prep1<<<2048, 256>>>(Wx, Wh);
    k_prep2<<<512, 256>>>(W_mu, W_std);
    k_prep3<<<512, 256>>>(W_r1);

    float disc = 1.0f;
    for (int t = 0; t < TSTEPS; ++t) {
        int par = t & 1;
        int parn = par ^ 1;
        k1_gru<<<dim3(BDIM / BM, HDIM / BN), 256, SM1>>>(par, Wx, b_gru, acts + (size_t)t * BDIM);
        k2_latent<<<dim3(BDIM / BM, SDIM / BN), 256, SM2>>>(parn, b_mu, b_std,
                                                            noise + (size_t)t * BDIM * SDIM);
        k3_reward<<<dim3(BDIM / BM, RHDIM / BN), 256, SM3>>>(parn, b_r1);
        k4_reduce<<<BDIM, 128>>>(parn, w_r2, b_r2, disc);
        disc *= 0.99f;
    }
    k_final<<<16, 256>>>(out);
}